// round 16
// baseline (speedup 1.0000x reference)
#include <cuda_runtime.h>
#include <cuda_fp16.h>
#include <cstdint>
#include <cstddef>

#define NB  4
#define SEQ 4096
#define DIM 1024
#define MTOT (NB * SEQ)
#define NQKV 3072

// ---------------------------------------------------------------------------
// Scratch (static device globals; runtime allocation is forbidden)
// ---------------------------------------------------------------------------
__device__ __half g_X  [(size_t)MTOT * DIM];
__device__ __half g_W  [(size_t)NQKV * DIM];     // [Wq;Wk;Wv] rows
__device__ float  g_B3 [NQKV];                   // [bq;bk;bv]
__device__ __half g_QKV[(size_t)MTOT * NQKV];    // Q | K | V column blocks
__device__ __half g_E  [(size_t)NB * SEQ * SEQ]; // exp(scores), unnormalized
__device__ float  g_RS [(size_t)MTOT];           // row sums of E

// exp(x/32) = exp2(x * (1/32) * log2(e))
#define EXP_SCALE 0.045083183f

// ---------------------------------------------------------------------------
// PTX helpers
// ---------------------------------------------------------------------------
__device__ __forceinline__ uint32_t s2u(const void* p) {
    uint32_t a;
    asm("{ .reg .u64 t; cvta.to.shared.u64 t, %1; cvt.u32.u64 %0, t; }"
        : "=r"(a) : "l"(p));
    return a;
}
__device__ __forceinline__ void cpasync16(uint32_t s, const void* g) {
    asm volatile("cp.async.cg.shared.global [%0], [%1], 16;"
                 :: "r"(s), "l"(g) : "memory");
}
__device__ __forceinline__ void cp_commit() {
    asm volatile("cp.async.commit_group;" ::: "memory");
}
__device__ __forceinline__ void ldsm4(uint32_t& r0, uint32_t& r1,
                                      uint32_t& r2, uint32_t& r3, uint32_t a) {
    asm volatile("ldmatrix.sync.aligned.m8n8.x4.shared.b16 {%0,%1,%2,%3}, [%4];"
                 : "=r"(r0), "=r"(r1), "=r"(r2), "=r"(r3) : "r"(a));
}
__device__ __forceinline__ void ldsm4t(uint32_t& r0, uint32_t& r1,
                                       uint32_t& r2, uint32_t& r3, uint32_t a) {
    asm volatile("ldmatrix.sync.aligned.m8n8.x4.trans.shared.b16 {%0,%1,%2,%3}, [%4];"
                 : "=r"(r0), "=r"(r1), "=r"(r2), "=r"(r3) : "r"(a));
}
__device__ __forceinline__ void mma16816(float* c, const uint32_t* a,
                                         const uint32_t* b) {
    asm volatile(
        "mma.sync.aligned.m16n8k16.row.col.f32.f16.f16.f32 "
        "{%0,%1,%2,%3}, {%4,%5,%6,%7}, {%8,%9}, {%0,%1,%2,%3};"
        : "+f"(c[0]), "+f"(c[1]), "+f"(c[2]), "+f"(c[3])
        : "r"(a[0]), "r"(a[1]), "r"(a[2]), "r"(a[3]), "r"(b[0]), "r"(b[1]));
}
__device__ __forceinline__ uint32_t pr2h(__half a, __half b) {
    return ((uint32_t)__half_as_ushort(b) << 16) | __half_as_ushort(a);
}

// ---------------------------------------------------------------------------
// fp16 GEMM:  C[M,N] = A[M,K] * op(B)
// BTRANS=false: B rows are N-indexed, K contiguous (C = A*B^T).
// BTRANS=true : B rows are K-indexed, N contiguous (C = A*B), ldmatrix.trans.
// 256 threads (8 warps, 4x2), CTA tile 128x128, K slab 64, warp tile 32x64.
// cp.async 3-stage pipeline, 2 CTAs/SM -> 16 warps/SM (4 per SMSP).
// lda/ldb = global row strides. ksplit: blockIdx.z = batch*ksplit + k-half;
// each half covers K/ksplit (EPI 4 accumulates via fp32 atomicAdd).
// EPI 0: +bias -> fp16.
// EPI 3: exp2(acc*alpha) -> fp16, atomicAdd row sums into RS.
// EPI 4: atomicAdd(acc * (1/RS[row])) -> fp32.
// ---------------------------------------------------------------------------
constexpr int BM = 128, BN = 128, BK = 64;
constexpr int PITCH_A  = 144;               // 128 B data + 16 pad
constexpr int ARR_A    = 128 * PITCH_A;     // 18432
constexpr int PITCH_BT = 272;               // 256 B data + 16 pad
constexpr int ARR_BT   = 64 * PITCH_BT;     // 17408
constexpr int SM_STD = 3 * (ARR_A + ARR_A);   // 110592
constexpr int SM_TRN = 3 * (ARR_A + ARR_BT);  // 107520

template <int EPI, bool BTRANS>
__global__ void __launch_bounds__(256, 2)
gemm_mma(const __half* __restrict__ Ag, const __half* __restrict__ Bg,
         const float* __restrict__ bias, float* __restrict__ RS,
         __half* __restrict__ Ch, float* __restrict__ Cf,
         int N, int K, int lda, int ldb, int ksplit,
         size_t sA, size_t sB, size_t sC, float alpha)
{
    constexpr int ARRB  = BTRANS ? ARR_BT : ARR_A;
    constexpr int STAGE = ARR_A + ARRB;

    extern __shared__ char smem[];
    const int tid  = threadIdx.x;
    const int lane = tid & 31, warp = tid >> 5;
    const int wm = warp >> 1, wn = warp & 1;     // 4x2 grid of 32x64 tiles
    const int m0 = blockIdx.y * BM, n0 = blockIdx.x * BN;
    const int zb = blockIdx.z / ksplit;
    const int kh = blockIdx.z - zb * ksplit;
    const int Keff = K / ksplit;

    const __half* A = Ag + (size_t)zb * sA + (size_t)kh * Keff;
    const __half* B = Bg + (size_t)zb * sB +
                      (BTRANS ? (size_t)kh * Keff * ldb : (size_t)kh * Keff);
    const uint32_t sbase = s2u(smem);

    // ---- cp.async per-thread bases (4 slots each for A and B) ----
    const __half* gA = A + (size_t)(m0 + (tid >> 3)) * lda + (tid & 7) * 8;
    const uint32_t sA0 = (tid >> 3) * PITCH_A + (tid & 7) * 16;
    const __half* gB;
    uint32_t sB0;
    if (BTRANS) {
        gB  = B + (size_t)(tid >> 4) * ldb + n0 + (tid & 15) * 8;
        sB0 = (tid >> 4) * PITCH_BT + (tid & 15) * 16;
    } else {
        gB  = B + (size_t)(n0 + (tid >> 3)) * ldb + (tid & 7) * 8;
        sB0 = (tid >> 3) * PITCH_A + (tid & 7) * 16;
    }

    const int NS = Keff / BK;

    auto issue = [&](int slab) {
        const uint32_t st = sbase + (slab % 3) * STAGE;
        const __half* ga = gA + (size_t)slab * BK;
#pragma unroll
        for (int j = 0; j < 4; j++)
            cpasync16(st + sA0 + j * (32 * PITCH_A), ga + (size_t)j * 32 * lda);
        if (BTRANS) {
            const __half* gb = gB + (size_t)slab * BK * ldb;
#pragma unroll
            for (int j = 0; j < 4; j++)
                cpasync16(st + ARR_A + sB0 + j * (16 * PITCH_BT),
                          gb + (size_t)j * 16 * ldb);
        } else {
            const __half* gb = gB + (size_t)slab * BK;
#pragma unroll
            for (int j = 0; j < 4; j++)
                cpasync16(st + ARR_A + sB0 + j * (32 * PITCH_A),
                          gb + (size_t)j * 32 * ldb);
        }
    };

    issue(0); cp_commit();
    issue(1); cp_commit();

    float acc[2][8][4];
#pragma unroll
    for (int t = 0; t < 2; t++)
#pragma unroll
        for (int nt = 0; nt < 8; nt++)
#pragma unroll
            for (int f = 0; f < 4; f++) acc[t][nt][f] = 0.0f;

    const uint32_t aoff = (uint32_t)((wm * 32 + (lane & 15)) * PITCH_A +
                                     ((lane >> 4) << 4));
    uint32_t boff;
    if (BTRANS)
        boff = (uint32_t)(((((lane >> 3) & 1) << 3) + (lane & 7)) * PITCH_BT +
                          ((lane >> 4) << 4) + wn * 128);
    else
        boff = (uint32_t)((wn * 64 + ((lane >> 4) << 3) + (lane & 7)) * PITCH_A +
                          (((lane >> 3) & 1) << 4));

    for (int s = 0; s < NS; s++) {
        asm volatile("cp.async.wait_group 1;" ::: "memory");
        __syncthreads();
        if (s + 2 < NS) issue(s + 2);
        cp_commit();

        const uint32_t st = sbase + (s % 3) * STAGE;
#pragma unroll
        for (int kk = 0; kk < 4; kk++) {
            uint32_t bh[16];
#pragma unroll
            for (int p = 0; p < 4; p++) {
                if (BTRANS)
                    ldsm4t(bh[4*p], bh[4*p+1], bh[4*p+2], bh[4*p+3],
                           st + ARR_A + boff + kk * (16 * PITCH_BT) + p * 32);
                else
                    ldsm4(bh[4*p], bh[4*p+1], bh[4*p+2], bh[4*p+3],
                          st + ARR_A + boff + kk * 32 + p * (16 * PITCH_A));
            }
#pragma unroll
            for (int t = 0; t < 2; t++) {
                uint32_t ah[4];
                ldsm4(ah[0], ah[1], ah[2], ah[3],
                      st + aoff + t * (16 * PITCH_A) + kk * 32);
#pragma unroll
                for (int nt = 0; nt < 8; nt++)
                    mma16816(acc[t][nt], ah, &bh[2 * nt]);
            }
        }
        __syncthreads();
    }
    asm volatile("cp.async.wait_group 0;" ::: "memory");

    // ---- EPI 4: stage reciprocal row sums through (now idle) smem ----
    float* srs = (float*)smem;
    if (EPI == 4) {
        __syncthreads();
        if (tid < 128)
            srs[tid] = 1.0f / RS[(size_t)zb * SEQ + m0 + tid];
        __syncthreads();
    }

    // ---- epilogue ----
    const int mrow = lane >> 2;
    const int ncol = (lane & 3) * 2;
    float rsum[2][2] = {{0.0f, 0.0f}, {0.0f, 0.0f}};   // EPI 3 row partials
#pragma unroll
    for (int t = 0; t < 2; t++)
#pragma unroll
        for (int nt = 0; nt < 8; nt++)
#pragma unroll
            for (int hp = 0; hp < 2; hp++) {
                int ml = wm * 32 + t * 16 + mrow + hp * 8;   // row within CTA
                int m = m0 + ml;
                int n = n0 + wn * 64 + nt * 8 + ncol;
                float v0 = acc[t][nt][hp * 2 + 0];
                float v1 = acc[t][nt][hp * 2 + 1];
                size_t off = (size_t)zb * sC + (size_t)m * N + n;
                if (EPI == 0) {
                    v0 += bias[n]; v1 += bias[n + 1];
                    *(uint32_t*)(Ch + off) = pr2h(__float2half(v0), __float2half(v1));
                } else if (EPI == 3) {
                    float e0 = exp2f(v0 * alpha);
                    float e1 = exp2f(v1 * alpha);
                    rsum[t][hp] += e0 + e1;
                    *(uint32_t*)(Ch + off) = pr2h(__float2half(e0), __float2half(e1));
                } else {
                    float inv = srs[ml];
                    atomicAdd(Cf + off,     v0 * inv);
                    atomicAdd(Cf + off + 1, v1 * inv);
                }
            }

    if (EPI == 3) {
        // reduce across the 4 lanes sharing each row, then one atomic per row
#pragma unroll
        for (int t = 0; t < 2; t++)
#pragma unroll
            for (int hp = 0; hp < 2; hp++) {
                float v = rsum[t][hp];
                v += __shfl_xor_sync(0xffffffffu, v, 1);
                v += __shfl_xor_sync(0xffffffffu, v, 2);
                if ((lane & 3) == 0) {
                    int m = m0 + wm * 32 + t * 16 + mrow + hp * 8;
                    atomicAdd(RS + (size_t)zb * SEQ + m, v);
                }
            }
    }
}

// ---------------------------------------------------------------------------
// fp32 -> fp16 convert, float4-vectorized (X)
// ---------------------------------------------------------------------------
__global__ void conv_kernel(const float* __restrict__ x,
                            __half* __restrict__ h, size_t n4)
{
    size_t i  = (size_t)blockIdx.x * blockDim.x + threadIdx.x;
    size_t st = (size_t)gridDim.x * blockDim.x;
    for (; i < n4; i += st) {
        float4 v = ((const float4*)x)[i];
        ((uint2*)h)[i] = make_uint2(
            pr2h(__float2half(v.x), __float2half(v.y)),
            pr2h(__float2half(v.z), __float2half(v.w)));
    }
}

// Concatenate 3 weight matrices -> g_W (fp16) and 3 biases -> g_B3 (fp32).
__global__ void conv3_kernel(const float* __restrict__ w0,
                             const float* __restrict__ w1,
                             const float* __restrict__ w2,
                             const float* __restrict__ b0,
                             const float* __restrict__ b1,
                             const float* __restrict__ b2,
                             __half* __restrict__ W, float* __restrict__ B3,
                             size_t n4)
{
    const float* x = (blockIdx.y == 0) ? w0 : (blockIdx.y == 1) ? w1 : w2;
    __half*      h = W + (size_t)blockIdx.y * DIM * DIM;
    size_t i  = (size_t)blockIdx.x * blockDim.x + threadIdx.x;
    size_t st = (size_t)gridDim.x * blockDim.x;
    for (; i < n4; i += st) {
        float4 v = ((const float4*)x)[i];
        ((uint2*)h)[i] = make_uint2(
            pr2h(__float2half(v.x), __float2half(v.y)),
            pr2h(__float2half(v.z), __float2half(v.w)));
    }
    if (blockIdx.x == 0) {
        const float* b = (blockIdx.y == 0) ? b0 : (blockIdx.y == 1) ? b1 : b2;
        for (int j = threadIdx.x; j < DIM; j += blockDim.x)
            B3[blockIdx.y * DIM + j] = b[j];
    }
}

// ---------------------------------------------------------------------------
extern "C" void kernel_launch(void* const* d_in, const int* in_sizes, int n_in,
                              void* d_out, int out_size)
{
    const float* X  = (const float*)d_in[0];
    const float* Wq = (const float*)d_in[1];
    const float* bq = (const float*)d_in[2];
    const float* Wk = (const float*)d_in[3];
    const float* bk = (const float*)d_in[4];
    const float* Wv = (const float*)d_in[5];
    const float* bv = (const float*)d_in[6];
    float* out = (float*)d_out;

    __half *Xp, *W, *QKV, *E;
    float *B3, *RS;
    cudaGetSymbolAddress((void**)&Xp,  g_X);
    cudaGetSymbolAddress((void**)&W,   g_W);
    cudaGetSymbolAddress((void**)&B3,  g_B3);
    cudaGetSymbolAddress((void**)&QKV, g_QKV);
    cudaGetSymbolAddress((void**)&E,   g_E);
    cudaGetSymbolAddress((void**)&RS,  g_RS);

    cudaFuncSetAttribute(gemm_mma<0, false>, cudaFuncAttributeMaxDynamicSharedMemorySize, SM_STD);
    cudaFuncSetAttribute(gemm_mma<3, false>, cudaFuncAttributeMaxDynamicSharedMemorySize, SM_STD);
    cudaFuncSetAttribute(gemm_mma<4, true>,  cudaFuncAttributeMaxDynamicSharedMemorySize, SM_TRN);

    // 0) zero accumulator targets (graph-capturable async memsets)
    cudaMemsetAsync(RS,  0, (size_t)MTOT * sizeof(float));
    cudaMemsetAsync(out, 0, (size_t)MTOT * DIM * sizeof(float));

    // 1) operand prep -> fp16 (X; concatenated W + bias)
    conv_kernel<<<2048, 256>>>(X, Xp, (size_t)MTOT * DIM / 4);
    dim3 gw(512, 3);
    conv3_kernel<<<gw, 256>>>(Wq, Wk, Wv, bq, bk, bv, W, B3, (size_t)DIM * DIM / 4);

    // 2) fused projections: QKV[m, 0:3072] = X*[Wq;Wk;Wv]^T + [bq;bk;bv]
    dim3 gp(NQKV / BN, MTOT / BM, 1);
    gemm_mma<0, false><<<gp, 256, SM_STD>>>(Xp, W, B3, nullptr, QKV, nullptr,
                                            NQKV, DIM, DIM, DIM, 1, 0, 0, 0, 1.0f);

    // 3) E = exp(Q K^T / 32) -> fp16 + fused row sums into RS, per batch
    dim3 gs(SEQ / BN, SEQ / BM, NB);
    gemm_mma<3, false><<<gs, 256, SM_STD>>>(QKV, QKV + DIM, nullptr, RS, E, nullptr,
                                            SEQ, DIM, NQKV, NQKV, 1,
                                            (size_t)SEQ * NQKV, (size_t)SEQ * NQKV,
                                            (size_t)SEQ * SEQ, EXP_SCALE);

    // 4) out += (E_half * V_half) / rowsum   (split-K=2, fp32 atomics)
    dim3 go(DIM / BN, SEQ / BM, NB * 2);
    gemm_mma<4, true><<<go, 256, SM_TRN>>>(E, QKV + 2 * DIM, nullptr, RS, nullptr, out,
                                           DIM, SEQ, SEQ, NQKV, 2,
                                           (size_t)SEQ * SEQ, (size_t)SEQ * NQKV,
                                           (size_t)SEQ * DIM, 1.0f);
}